// round 6
// baseline (speedup 1.0000x reference)
#include <cuda_runtime.h>

// ---------------- problem constants ----------------
#define Ln   256   // sequence length
#define Cn   64    // channels (= HID)
#define Hn   8     // heads
#define NUMn 64    // memory steps
#define Bn   32    // batch
#define RB   64    // query rows per CTA
#define NT   256   // threads per CTA
#define SK   65    // padded row stride for 64-wide matrices
#define SSs  257   // padded row stride for the 256-wide score matrix

// ---------------- shared memory layout (floats) ----------------
#define OFF_K 0                       // keys   [256][SK]
#define OFF_V (256*SK)                // values [256][SK]   (mode 0 aliases OFF_K)
#define OFF_Q (OFF_V + 256*SK)        // queries [64][SK]
#define OFF_S (OFF_Q + 64*SK)         // scores [64][SSs]  (also x-staging [256][64])
#define OFF_C (OFF_S + 64*SSs)        // const area (960 floats)
#define SMEM_FLOATS (OFF_C + 960)
#define SMEM_BYTES  (SMEM_FLOATS * 4)

// FFN scratch lives in the (freed) value-buffer region
#define OFF_W1 OFF_V
#define OFF_W2 (OFF_V + 64*SK)
#define OFF_Z  (OFF_V + 128*SK)
#define OFF_HH (OFF_V + 192*SK)

// const-area sub offsets
#define C_W   (OFF_C + 0)    // raw projection weight  [8][8][8] = 512
#define C_B   (OFF_C + 512)  // raw projection bias 64
#define C_G0  (OFF_C + 576)
#define C_B0  (OFF_C + 640)
#define C_G1  (OFF_C + 704)
#define C_B1  (OFF_C + 768)
#define C_F1B (OFF_C + 832)
#define C_F2B (OFF_C + 896)

struct AttnParams {
  const float *x, *emb;
  const float *Wk, *bk, *Wq, *bq, *Wv, *bv;
  const float *g0x, *b0x, *g1x, *b1x;
  const float *g0k, *b0k, *g1k, *b1k;
  const float *g0q, *b0q, *g1q, *b1q;
  const float *fx1w, *fx1b, *fx2w, *fx2b;
  const float *fk1w, *fk1b, *fk2w, *fk2b;
  const float *fq1w, *fq1b, *fq2w, *fq2b;
  float *K, *Q, *V;
  int t;
};

__device__ __forceinline__ float hmax16(float v) {
  v = fmaxf(v, __shfl_xor_sync(0xffffffffu, v, 1));
  v = fmaxf(v, __shfl_xor_sync(0xffffffffu, v, 2));
  v = fmaxf(v, __shfl_xor_sync(0xffffffffu, v, 4));
  v = fmaxf(v, __shfl_xor_sync(0xffffffffu, v, 8));
  return v;
}
__device__ __forceinline__ float hsum16(float v) {
  v += __shfl_xor_sync(0xffffffffu, v, 1);
  v += __shfl_xor_sync(0xffffffffu, v, 2);
  v += __shfl_xor_sync(0xffffffffu, v, 4);
  v += __shfl_xor_sync(0xffffffffu, v, 8);
  return v;
}

// copy nrows x 64 contiguous floats from gmem into smem with SK padding
__device__ __forceinline__ void load_rows(float* dst, const float* __restrict__ src,
                                          int nrows, int tid) {
  const int n4 = nrows * 16;
  const float4* s4 = (const float4*)src;
  for (int i = tid; i < n4; i += NT) {
    float4 v = __ldg(s4 + i);
    int l = i >> 4, c = (i & 15) << 2;
    float* d = dst + l * SK + c;
    d[0] = v.x; d[1] = v.y; d[2] = v.z; d[3] = v.w;
  }
}

// One CTA: 64 query rows of one (batch, mode) cross-attention step.
// mode 0: k-attn  (keys = raw k, values = raw k, queries = Q[t-1])
// mode 1: q-attn  (keys = K[t-1], values = raw q, queries = raw q)
// mode 2: v-attn  (keys = K[t],   values = raw v, queries = Q[t])
__global__ __launch_bounds__(NT, 1)
void attn_step_kernel(AttnParams p, int modeBase) {
  extern __shared__ float sm[];
  const int tid = threadIdx.x;
  const int rb  = blockIdx.x * RB;
  const int b   = blockIdx.y;
  const int mode = modeBase + (int)blockIdx.z;
  const int t = p.t;

  const size_t bOff    = (size_t)b * NUMn * Ln * Cn;
  const size_t curOff  = bOff + (size_t)t * Ln * Cn;
  const size_t prevOff = bOff + (size_t)(t - 1) * Ln * Cn;

  const float *rawW, *rawB, *g0, *b0, *g1, *b1, *w1, *fb1, *w2, *fb2;
  const float *keysG = 0, *qG = 0;
  float* outG;
  if (mode == 0) {
    rawW = p.Wk; rawB = p.bk;
    g0 = p.g0k; b0 = p.b0k; g1 = p.g1k; b1 = p.b1k;
    w1 = p.fk1w; fb1 = p.fk1b; w2 = p.fk2w; fb2 = p.fk2b;
    qG = p.Q + prevOff;
    outG = p.K + curOff;
  } else if (mode == 1) {
    rawW = p.Wq; rawB = p.bq;
    g0 = p.g0q; b0 = p.b0q; g1 = p.g1q; b1 = p.b1q;
    w1 = p.fq1w; fb1 = p.fq1b; w2 = p.fq2w; fb2 = p.fq2b;
    keysG = p.K + prevOff;
    outG = p.Q + curOff;
  } else {
    rawW = p.Wv; rawB = p.bv;
    g0 = p.g0x; b0 = p.b0x; g1 = p.g1x; b1 = p.b1x;
    w1 = p.fx1w; fb1 = p.fx1b; w2 = p.fx2w; fb2 = p.fx2b;
    keysG = p.K + curOff;
    qG = p.Q + curOff;
    outG = p.V + curOff;
  }

  // ---- const area ----
  for (int i = tid; i < 512; i += NT) sm[C_W + i] = __ldg(rawW + i);
  if (tid < 64) {
    sm[C_B   + tid] = __ldg(rawB + tid);
    sm[C_G0  + tid] = __ldg(g0 + tid);
    sm[C_B0  + tid] = __ldg(b0 + tid);
    sm[C_G1  + tid] = __ldg(g1 + tid);
    sm[C_B1  + tid] = __ldg(b1 + tid);
    sm[C_F1B + tid] = __ldg(fb1 + tid);
    sm[C_F2B + tid] = __ldg(fb2 + tid);
  }

  // ---- stage x[b,t] + emb into OFF_S (stride 64) ----
  {
    const float4* xs = (const float4*)(p.x + curOff);
    const float4* es = (const float4*)p.emb;
    float4* d = (float4*)(sm + OFF_S);
    for (int i = tid; i < Ln * Cn / 4; i += NT) {
      float4 xv = __ldg(xs + i);
      float4 ev = __ldg(es + i);
      xv.x += ev.x; xv.y += ev.y; xv.z += ev.z; xv.w += ev.w;
      d[i] = xv;
    }
  }

  // ---- load global keys / queries ----
  if (mode == 0) {
    load_rows(sm + OFF_Q, qG + (size_t)rb * Cn, RB, tid);
  } else {
    load_rows(sm + OFF_K, keysG, Ln, tid);
    if (mode == 2) load_rows(sm + OFF_Q, qG + (size_t)rb * Cn, RB, tid);
  }
  __syncthreads();

  // ---- fused raw projection: raw[l][h*8+e] = sum_d xe[l][h*8+d]*W[h][d][e] + b[h][e] ----
  {
    float* rawDst = (mode == 0) ? (sm + OFF_K) : (sm + OFF_V);
    for (int task = tid; task < Ln * Hn; task += NT) {
      int l = task >> 3, h = task & 7;
      const float* xe = sm + OFF_S + l * Cn + h * 8;
      const float* W  = sm + C_W + h * 64;
      float acc[8];
      #pragma unroll
      for (int e = 0; e < 8; e++) acc[e] = sm[C_B + h * 8 + e];
      #pragma unroll
      for (int d = 0; d < 8; d++) {
        float xv = xe[d];
        #pragma unroll
        for (int e = 0; e < 8; e++) acc[e] = fmaf(xv, W[d * 8 + e], acc[e]);
      }
      float* o = rawDst + l * SK + h * 8;
      #pragma unroll
      for (int e = 0; e < 8; e++) o[e] = acc[e];
    }
  }
  __syncthreads();

  const int rg = tid >> 4;   // row group: rows rg*4 .. rg*4+3 (local)
  const int cg = tid & 15;   // col group: cols cg + 16*j

  // ---- S = Q @ K^T  (64 x 256, k = 64) ----
  float accS[4][16];
  #pragma unroll
  for (int i = 0; i < 4; i++)
    #pragma unroll
    for (int j = 0; j < 16; j++) accS[i][j] = 0.f;
  {
    const float* qbase = (mode == 1) ? (sm + OFF_V + rb * SK) : (sm + OFF_Q);
    const float* q0 = qbase + (rg * 4 + 0) * SK;
    const float* q1 = qbase + (rg * 4 + 1) * SK;
    const float* q2 = qbase + (rg * 4 + 2) * SK;
    const float* q3 = qbase + (rg * 4 + 3) * SK;
    const float* kc = sm + OFF_K + cg * SK;
    #pragma unroll 4
    for (int d = 0; d < 64; d++) {
      float a0 = q0[d], a1 = q1[d], a2 = q2[d], a3 = q3[d];
      #pragma unroll
      for (int j = 0; j < 16; j++) {
        float kv = kc[j * (16 * SK) + d];
        accS[0][j] = fmaf(a0, kv, accS[0][j]);
        accS[1][j] = fmaf(a1, kv, accS[1][j]);
        accS[2][j] = fmaf(a2, kv, accS[2][j]);
        accS[3][j] = fmaf(a3, kv, accS[3][j]);
      }
    }
  }

  // ---- softmax over full row (16 lanes x 16 cols), folded /sqrt(64) ----
  #pragma unroll
  for (int i = 0; i < 4; i++) {
    float m = accS[i][0];
    #pragma unroll
    for (int j = 1; j < 16; j++) m = fmaxf(m, accS[i][j]);
    m = hmax16(m);
    float s = 0.f;
    #pragma unroll
    for (int j = 0; j < 16; j++) {
      float e = __expf(accS[i][j] - m);
      accS[i][j] = e;
      s += e;
    }
    s = hsum16(s);
    float sc = 0.125f / s;   // softmax then /sqrt(64)
    float* pr = sm + OFF_S + (rg * 4 + i) * SSs + cg;
    #pragma unroll
    for (int j = 0; j < 16; j++) pr[16 * j] = accS[i][j] * sc;
  }
  __syncthreads();

  // ---- O = P @ V  (64 x 64, k = 256) ----
  const float* Vs = (mode == 0) ? (sm + OFF_K) : (sm + OFF_V);
  float acc2[4][4];
  #pragma unroll
  for (int i = 0; i < 4; i++)
    #pragma unroll
    for (int c2 = 0; c2 < 4; c2++) acc2[i][c2] = 0.f;
  {
    const float* p0 = sm + OFF_S + (rg * 4 + 0) * SSs;
    const float* p1 = sm + OFF_S + (rg * 4 + 1) * SSs;
    const float* p2 = sm + OFF_S + (rg * 4 + 2) * SSs;
    const float* p3 = sm + OFF_S + (rg * 4 + 3) * SSs;
    const float* vc = Vs + cg;
    #pragma unroll 4
    for (int j = 0; j < 256; j++) {
      float a0 = p0[j], a1 = p1[j], a2 = p2[j], a3 = p3[j];
      #pragma unroll
      for (int c2 = 0; c2 < 4; c2++) {
        float vv = vc[j * SK + 16 * c2];
        acc2[0][c2] = fmaf(a0, vv, acc2[0][c2]);
        acc2[1][c2] = fmaf(a1, vv, acc2[1][c2]);
        acc2[2][c2] = fmaf(a2, vv, acc2[2][c2]);
        acc2[3][c2] = fmaf(a3, vv, acc2[3][c2]);
      }
    }
  }

  // ---- residual (+V row) and LayerNorm 1 ----
  float z[4][4];
  {
    float sum[4], sq[4];
    #pragma unroll
    for (int i = 0; i < 4; i++) { sum[i] = 0.f; sq[i] = 0.f; }
    #pragma unroll
    for (int i = 0; i < 4; i++) {
      const float* vr = Vs + (rb + rg * 4 + i) * SK + cg;
      #pragma unroll
      for (int c2 = 0; c2 < 4; c2++) {
        float o = acc2[i][c2] + vr[16 * c2];
        z[i][c2] = o;
        sum[i] += o;
        sq[i]  += o * o;
      }
    }
    #pragma unroll
    for (int i = 0; i < 4; i++) { sum[i] = hsum16(sum[i]); sq[i] = hsum16(sq[i]); }
    #pragma unroll
    for (int i = 0; i < 4; i++) {
      float mean = sum[i] * (1.f / 64.f);
      float var  = sq[i] * (1.f / 64.f) - mean * mean;
      float rs = rsqrtf(var + 1e-5f);
      #pragma unroll
      for (int c2 = 0; c2 < 4; c2++) {
        int c = cg + 16 * c2;
        z[i][c2] = (z[i][c2] - mean) * rs * sm[C_G0 + c] + sm[C_B0 + c];
      }
    }
  }
  __syncthreads();  // all reads of OFF_V-region done; safe to reuse it

  // ---- stage z and FFN weights into (reused) OFF_V region ----
  #pragma unroll
  for (int i = 0; i < 4; i++)
    #pragma unroll
    for (int c2 = 0; c2 < 4; c2++)
      sm[OFF_Z + (rg * 4 + i) * SK + cg + 16 * c2] = z[i][c2];
  {
    const float4* w1s = (const float4*)w1;
    const float4* w2s = (const float4*)w2;
    for (int i = tid; i < 1024; i += NT) {
      int l = i >> 4, c = (i & 15) << 2;
      float4 v = __ldg(w1s + i);
      float* dd = sm + OFF_W1 + l * SK + c;
      dd[0] = v.x; dd[1] = v.y; dd[2] = v.z; dd[3] = v.w;
      v = __ldg(w2s + i);
      dd = sm + OFF_W2 + l * SK + c;
      dd[0] = v.x; dd[1] = v.y; dd[2] = v.z; dd[3] = v.w;
    }
  }
  __syncthreads();

  // ---- FFN layer 1: h = relu(z @ W1 + b1) ----
  float hreg[4][4];
  #pragma unroll
  for (int i = 0; i < 4; i++)
    #pragma unroll
    for (int c2 = 0; c2 < 4; c2++) hreg[i][c2] = sm[C_F1B + cg + 16 * c2];
  {
    const float* z0 = sm + OFF_Z + (rg * 4 + 0) * SK;
    const float* z1 = sm + OFF_Z + (rg * 4 + 1) * SK;
    const float* z2 = sm + OFF_Z + (rg * 4 + 2) * SK;
    const float* z3 = sm + OFF_Z + (rg * 4 + 3) * SK;
    const float* wc = sm + OFF_W1 + cg;
    #pragma unroll 4
    for (int d = 0; d < 64; d++) {
      float a0 = z0[d], a1 = z1[d], a2 = z2[d], a3 = z3[d];
      #pragma unroll
      for (int c2 = 0; c2 < 4; c2++) {
        float wv = wc[d * SK + 16 * c2];
        hreg[0][c2] = fmaf(a0, wv, hreg[0][c2]);
        hreg[1][c2] = fmaf(a1, wv, hreg[1][c2]);
        hreg[2][c2] = fmaf(a2, wv, hreg[2][c2]);
        hreg[3][c2] = fmaf(a3, wv, hreg[3][c2]);
      }
    }
  }
  #pragma unroll
  for (int i = 0; i < 4; i++)
    #pragma unroll
    for (int c2 = 0; c2 < 4; c2++)
      sm[OFF_HH + (rg * 4 + i) * SK + cg + 16 * c2] = fmaxf(hreg[i][c2], 0.f);
  __syncthreads();

  // ---- FFN layer 2 + residual + LayerNorm 2 + global write ----
  float f[4][4];
  #pragma unroll
  for (int i = 0; i < 4; i++)
    #pragma unroll
    for (int c2 = 0; c2 < 4; c2++) f[i][c2] = sm[C_F2B + cg + 16 * c2];
  {
    const float* h0 = sm + OFF_HH + (rg * 4 + 0) * SK;
    const float* h1 = sm + OFF_HH + (rg * 4 + 1) * SK;
    const float* h2 = sm + OFF_HH + (rg * 4 + 2) * SK;
    const float* h3 = sm + OFF_HH + (rg * 4 + 3) * SK;
    const float* wc = sm + OFF_W2 + cg;
    #pragma unroll 4
    for (int d = 0; d < 64; d++) {
      float a0 = h0[d], a1 = h1[d], a2 = h2[d], a3 = h3[d];
      #pragma unroll
      for (int c2 = 0; c2 < 4; c2++) {
        float wv = wc[d * SK + 16 * c2];
        f[0][c2] = fmaf(a0, wv, f[0][c2]);
        f[1][c2] = fmaf(a1, wv, f[1][c2]);
        f[2][c2] = fmaf(a2, wv, f[2][c2]);
        f[3][c2] = fmaf(a3, wv, f[3][c2]);
      }
    }
  }
  {
    float sum[4], sq[4];
    #pragma unroll
    for (int i = 0; i < 4; i++) { sum[i] = 0.f; sq[i] = 0.f; }
    #pragma unroll
    for (int i = 0; i < 4; i++)
      #pragma unroll
      for (int c2 = 0; c2 < 4; c2++) {
        float o = f[i][c2] + z[i][c2];
        f[i][c2] = o;
        sum[i] += o;
        sq[i]  += o * o;
      }
    #pragma unroll
    for (int i = 0; i < 4; i++) { sum[i] = hsum16(sum[i]); sq[i] = hsum16(sq[i]); }
    #pragma unroll
    for (int i = 0; i < 4; i++) {
      float mean = sum[i] * (1.f / 64.f);
      float var  = sq[i] * (1.f / 64.f) - mean * mean;
      float rs = rsqrtf(var + 1e-5f);
      float* orow = outG + (size_t)(rb + rg * 4 + i) * Cn;
      #pragma unroll
      for (int c2 = 0; c2 < 4; c2++) {
        int c = cg + 16 * c2;
        orow[c] = (f[i][c2] - mean) * rs * sm[C_G1 + c] + sm[C_B1 + c];
      }
    }
  }
}

// t = 0: K/Q/V[:,0] are just the raw projections of x[:,0] + emb
__global__ __launch_bounds__(NT)
void proj0_kernel(AttnParams p) {
  const int b = blockIdx.x;
  const size_t off = (size_t)b * NUMn * Ln * Cn;  // t = 0
  const float* xs = p.x + off;
  for (int task = threadIdx.x; task < 3 * Ln * Hn; task += NT) {
    int pr = task / (Ln * Hn);
    int rem = task - pr * (Ln * Hn);
    int l = rem >> 3, h = rem & 7;
    const float *W, *bb;
    float* o;
    if (pr == 0)      { W = p.Wk; bb = p.bk; o = p.K; }
    else if (pr == 1) { W = p.Wq; bb = p.bq; o = p.Q; }
    else              { W = p.Wv; bb = p.bv; o = p.V; }
    W += h * 64; bb += h * 8;
    float acc[8];
    #pragma unroll
    for (int e = 0; e < 8; e++) acc[e] = __ldg(bb + e);
    #pragma unroll
    for (int d = 0; d < 8; d++) {
      float xv = __ldg(xs + l * Cn + h * 8 + d) + __ldg(p.emb + l * Cn + h * 8 + d);
      #pragma unroll
      for (int e = 0; e < 8; e++) acc[e] = fmaf(xv, __ldg(W + d * 8 + e), acc[e]);
    }
    float* dst = o + off + (size_t)l * Cn + h * 8;
    #pragma unroll
    for (int e = 0; e < 8; e++) dst[e] = acc[e];
  }
}

extern "C" void kernel_launch(void* const* d_in, const int* in_sizes, int n_in,
                              void* d_out, int out_size) {
  (void)in_sizes; (void)n_in; (void)out_size;
  AttnParams p;
  p.x    = (const float*)d_in[0];
  p.emb  = (const float*)d_in[1];
  p.Wk   = (const float*)d_in[2];   p.bk  = (const float*)d_in[3];
  p.Wq   = (const float*)d_in[4];   p.bq  = (const float*)d_in[5];
  p.Wv   = (const float*)d_in[6];   p.bv  = (const float*)d_in[7];
  p.g0x  = (const float*)d_in[8];   p.b0x = (const float*)d_in[9];
  p.g1x  = (const float*)d_in[10];  p.b1x = (const float*)d_in[11];
  p.g0k  = (const float*)d_in[12];  p.b0k = (const float*)d_in[13];
  p.g1k  = (const float*)d_in[14];  p.b1k = (const float*)d_in[15];
  p.g0q  = (const float*)d_in[16];  p.b0q = (const float*)d_in[17];
  p.g1q  = (const float*)d_in[18];  p.b1q = (const float*)d_in[19];
  p.fx1w = (const float*)d_in[20];  p.fx1b = (const float*)d_in[21];
  p.fx2w = (const float*)d_in[22];  p.fx2b = (const float*)d_in[23];
  p.fk1w = (const float*)d_in[24];  p.fk1b = (const float*)d_in[25];
  p.fk2w = (const float*)d_in[26];  p.fk2b = (const float*)d_in[27];
  p.fq1w = (const float*)d_in[28];  p.fq1b = (const float*)d_in[29];
  p.fq2w = (const float*)d_in[30];  p.fq2b = (const float*)d_in[31];

  float* out = (float*)d_out;
  const size_t sz = (size_t)Bn * NUMn * Ln * Cn;  // 33,554,432 per tensor
  p.K = out;
  p.Q = out + sz;
  p.V = out + 2 * sz;
  p.t = 0;

  cudaFuncSetAttribute((const void*)attn_step_kernel,
                       cudaFuncAttributeMaxDynamicSharedMemorySize, SMEM_BYTES);

  proj0_kernel<<<Bn, NT>>>(p);
  for (int t = 1; t < NUMn; t++) {
    p.t = t;
    // phase A: k-attn (mode 0) and q-attn (mode 1) in parallel
    attn_step_kernel<<<dim3(Ln / RB, Bn, 2), NT, SMEM_BYTES>>>(p, 0);
    // phase B: v-attn (mode 2) depends on new K and Q
    attn_step_kernel<<<dim3(Ln / RB, Bn, 1), NT, SMEM_BYTES>>>(p, 2);
  }
}

// round 8
// speedup vs baseline: 1.7060x; 1.7060x over previous
#include <cuda_runtime.h>

// ---------------- problem constants ----------------
#define Ln   256
#define Cn   64
#define NUMn 64
#define Bn   32
#define RB   64
#define NT   256
#define SA   68    // row stride (floats): 68*4 % 128 == 16 -> conflict-free LDS.128 phases
#define SV   260   // row stride (floats) for transposed V: 260*4 % 128 == 16

#define SZ (33554432ULL)  // B*NUM*L*C per tensor

// raw per-head projections of (x + emb) for all (b,t): [k|q|v][b][t][l][c]
__device__ float g_raw[3ULL * SZ];

// ---------------- shared memory layout (floats) ----------------
#define OFF_A  0                  // 256*SA = 17408 : K rows -> Vt[64][SV] -> {z,h,W1t,W2t}
#define OFF_Z  (OFF_A)
#define OFF_H  (OFF_A + 64*SA)
#define OFF_W1 (OFF_A + 128*SA)
#define OFF_W2 (OFF_A + 192*SA)
#define OFF_Q  (256*SA)           // 64*SA = 4352
#define OFF_C  (OFF_Q + 64*SA)
#define C_G0   (OFF_C + 0)
#define C_B0   (OFF_C + 64)
#define C_G1   (OFF_C + 128)
#define C_B1   (OFF_C + 192)
#define C_F1B  (OFF_C + 256)
#define C_F2B  (OFF_C + 320)
#define SMEM_FLOATS (OFF_C + 384)
#define SMEM_BYTES  (SMEM_FLOATS * 4)   // 88,576 bytes -> 2 CTAs/SM

struct AttnParams {
  const float *g0x, *b0x, *g1x, *b1x;
  const float *g0k, *b0k, *g1k, *b1k;
  const float *g0q, *b0q, *g1q, *b1q;
  const float *fx1w, *fx1b, *fx2w, *fx2b;
  const float *fk1w, *fk1b, *fk2w, *fk2b;
  const float *fq1w, *fq1b, *fq2w, *fq2b;
  float *K, *Q, *V;
  int t;
};

__device__ __forceinline__ float hmax16(float v) {
  v = fmaxf(v, __shfl_xor_sync(0xffffffffu, v, 1));
  v = fmaxf(v, __shfl_xor_sync(0xffffffffu, v, 2));
  v = fmaxf(v, __shfl_xor_sync(0xffffffffu, v, 4));
  v = fmaxf(v, __shfl_xor_sync(0xffffffffu, v, 8));
  return v;
}
__device__ __forceinline__ float hsum16(float v) {
  v += __shfl_xor_sync(0xffffffffu, v, 1);
  v += __shfl_xor_sync(0xffffffffu, v, 2);
  v += __shfl_xor_sync(0xffffffffu, v, 4);
  v += __shfl_xor_sync(0xffffffffu, v, 8);
  return v;
}

// ============ precompute: raw = proj(x + emb) for every (b,t); also K/Q/V at t=0 ============
__global__ __launch_bounds__(NT)
void precompute_raw_kernel(const float* __restrict__ x, const float* __restrict__ emb,
                           const float* __restrict__ Wk, const float* __restrict__ bk,
                           const float* __restrict__ Wq, const float* __restrict__ bq,
                           const float* __restrict__ Wv, const float* __restrict__ bv,
                           float* __restrict__ K, float* __restrict__ Q, float* __restrict__ V) {
  __shared__ float w[3 * 512 + 3 * 64];
  const int tid = threadIdx.x;
  for (int i = tid; i < 512; i += NT) {
    w[i]        = __ldg(Wk + i);
    w[512 + i]  = __ldg(Wq + i);
    w[1024 + i] = __ldg(Wv + i);
  }
  if (tid < 64) {
    w[1536 + tid] = __ldg(bk + tid);
    w[1600 + tid] = __ldg(bq + tid);
    w[1664 + tid] = __ldg(bv + tid);
  }
  __syncthreads();

  const size_t task = (size_t)blockIdx.x * NT + tid;  // over B*NUM*L*H = 4,194,304
  const int h = (int)(task & 7);
  const size_t row = task >> 3;                       // b*NUM*L + t*L + l
  const int l = (int)(row & 255);
  const int t = (int)((row >> 8) & 63);

  float xe[8];
  const float* xr = x + row * 64 + h * 8;
  const float* er = emb + l * 64 + h * 8;
  #pragma unroll
  for (int d = 0; d < 8; d++) xe[d] = __ldg(xr + d) + __ldg(er + d);

  float* outs0[3] = {K, Q, V};
  #pragma unroll
  for (int pidx = 0; pidx < 3; pidx++) {
    const float* W  = w + pidx * 512 + h * 64;
    const float* bb = w + 1536 + pidx * 64 + h * 8;
    float acc[8];
    #pragma unroll
    for (int e = 0; e < 8; e++) acc[e] = bb[e];
    #pragma unroll
    for (int d = 0; d < 8; d++) {
      float xv = xe[d];
      #pragma unroll
      for (int e = 0; e < 8; e++) acc[e] = fmaf(xv, W[d * 8 + e], acc[e]);
    }
    float* dst = g_raw + (size_t)pidx * SZ + row * 64 + h * 8;
    #pragma unroll
    for (int e = 0; e < 8; e++) dst[e] = acc[e];
    if (t == 0) {
      float* d2 = outs0[pidx] + row * 64 + h * 8;
      #pragma unroll
      for (int e = 0; e < 8; e++) d2[e] = acc[e];
    }
  }
}

// ============ attention step kernel ============
// mode 0: k-attn  keys=raw_k[t], vals=raw_k[t], queries=Q[t-1]   -> K[t]
// mode 1: q-attn  keys=K[t-1],   vals=raw_q[t], queries=raw_q[t] -> Q[t]
// mode 2: v-attn  keys=K[t],     vals=raw_v[t], queries=Q[t]     -> V[t]
__global__ __launch_bounds__(NT, 2)
void attn_step_kernel(AttnParams p, int modeBase) {
  extern __shared__ float sm[];
  const int tid = threadIdx.x;
  const int rb  = blockIdx.x * RB;
  const int b   = blockIdx.y;
  const int mode = modeBase + (int)blockIdx.z;
  const int t = p.t;

  const size_t bOff    = (size_t)b * NUMn * Ln * Cn;
  const size_t curOff  = bOff + (size_t)t * Ln * Cn;
  const size_t prevOff = bOff + (size_t)(t - 1) * Ln * Cn;
  const float* rawK = g_raw;
  const float* rawQ = g_raw + SZ;
  const float* rawV = g_raw + 2 * SZ;

  const float *g0, *b0, *g1, *b1, *w1, *fb1, *w2, *fb2;
  const float *keysG, *qG, *valsG;
  float* outG;
  if (mode == 0) {
    g0 = p.g0k; b0 = p.b0k; g1 = p.g1k; b1 = p.b1k;
    w1 = p.fk1w; fb1 = p.fk1b; w2 = p.fk2w; fb2 = p.fk2b;
    keysG = rawK + curOff; valsG = rawK + curOff;
    qG = p.Q + prevOff + (size_t)rb * Cn;
    outG = p.K + curOff;
  } else if (mode == 1) {
    g0 = p.g0q; b0 = p.b0q; g1 = p.g1q; b1 = p.b1q;
    w1 = p.fq1w; fb1 = p.fq1b; w2 = p.fq2w; fb2 = p.fq2b;
    keysG = p.K + prevOff; valsG = rawQ + curOff;
    qG = rawQ + curOff + (size_t)rb * Cn;
    outG = p.Q + curOff;
  } else {
    g0 = p.g0x; b0 = p.b0x; g1 = p.g1x; b1 = p.b1x;
    w1 = p.fx1w; fb1 = p.fx1b; w2 = p.fx2w; fb2 = p.fx2b;
    keysG = p.K + curOff; valsG = rawV + curOff;
    qG = p.Q + curOff + (size_t)rb * Cn;
    outG = p.V + curOff;
  }

  // ---- load K rows (stride SA), queries, consts ----
  {
    const float4* k4 = (const float4*)keysG;
    #pragma unroll
    for (int it = 0; it < 16; it++) {
      int i = tid + it * NT;
      float4 v = __ldg(k4 + i);
      int l = i >> 4, c = (i & 15) << 2;
      *(float4*)(sm + OFF_A + l * SA + c) = v;
    }
    const float4* q4 = (const float4*)qG;
    #pragma unroll
    for (int it = 0; it < 4; it++) {
      int i = tid + it * NT;
      float4 v = __ldg(q4 + i);
      int l = i >> 4, c = (i & 15) << 2;
      *(float4*)(sm + OFF_Q + l * SA + c) = v;
    }
    if (tid < 64) {
      sm[C_G0  + tid] = __ldg(g0 + tid);
      sm[C_B0  + tid] = __ldg(b0 + tid);
      sm[C_G1  + tid] = __ldg(g1 + tid);
      sm[C_B1  + tid] = __ldg(b1 + tid);
      sm[C_F1B + tid] = __ldg(fb1 + tid);
      sm[C_F2B + tid] = __ldg(fb2 + tid);
    }
  }
  __syncthreads();

  const int rg = tid >> 4;   // 16 row-groups of 4 rows
  const int cg = tid & 15;   // 16 col groups; S cols cg + 16*j

  // ---- S = Q @ K^T (64x256, k=64), LDS.128 over k ----
  float accS[4][16];
  #pragma unroll
  for (int i = 0; i < 4; i++)
    #pragma unroll
    for (int j = 0; j < 16; j++) accS[i][j] = 0.f;
  {
    const float* q0 = sm + OFF_Q + (rg * 4 + 0) * SA;
    const float* q1 = sm + OFF_Q + (rg * 4 + 1) * SA;
    const float* q2 = sm + OFF_Q + (rg * 4 + 2) * SA;
    const float* q3 = sm + OFF_Q + (rg * 4 + 3) * SA;
    const float* kc = sm + OFF_A + cg * SA;
    #pragma unroll 2
    for (int d4 = 0; d4 < 64; d4 += 4) {
      float4 a0 = *(const float4*)(q0 + d4);
      float4 a1 = *(const float4*)(q1 + d4);
      float4 a2 = *(const float4*)(q2 + d4);
      float4 a3 = *(const float4*)(q3 + d4);
      #pragma unroll
      for (int j = 0; j < 16; j++) {
        float4 kv = *(const float4*)(kc + j * (16 * SA) + d4);
        accS[0][j] = fmaf(a0.x, kv.x, fmaf(a0.y, kv.y, fmaf(a0.z, kv.z, fmaf(a0.w, kv.w, accS[0][j]))));
        accS[1][j] = fmaf(a1.x, kv.x, fmaf(a1.y, kv.y, fmaf(a1.z, kv.z, fmaf(a1.w, kv.w, accS[1][j]))));
        accS[2][j] = fmaf(a2.x, kv.x, fmaf(a2.y, kv.y, fmaf(a2.z, kv.z, fmaf(a2.w, kv.w, accS[2][j]))));
        accS[3][j] = fmaf(a3.x, kv.x, fmaf(a3.y, kv.y, fmaf(a3.z, kv.z, fmaf(a3.w, kv.w, accS[3][j]))));
      }
    }
  }
  __syncthreads();  // K reads done; A region free

  // ---- load V transposed into A: Vt[c][n]; LDG latency overlaps softmax ----
  {
    const float4* v4 = (const float4*)valsG;
    #pragma unroll
    for (int it = 0; it < 16; it++) {
      int i = tid + it * NT;
      float4 v = __ldg(v4 + i);
      int n = i >> 4, c4 = (i & 15) << 2;
      float* bp = sm + OFF_A + c4 * SV + n;
      bp[0 * SV] = v.x; bp[1 * SV] = v.y; bp[2 * SV] = v.z; bp[3 * SV] = v.w;
    }
  }

  // ---- softmax in registers, fold /sqrt(64) into probs ----
  #pragma unroll
  for (int i = 0; i < 4; i++) {
    float m = accS[i][0];
    #pragma unroll
    for (int j = 1; j < 16; j++) m = fmaxf(m, accS[i][j]);
    m = hmax16(m);
    float s = 0.f;
    #pragma unroll
    for (int j = 0; j < 16; j++) {
      float e = __expf(accS[i][j] - m);
      accS[i][j] = e;
      s += e;
    }
    s = hsum16(s);
    float sc = 0.125f / s;
    #pragma unroll
    for (int j = 0; j < 16; j++) accS[i][j] *= sc;
  }
  __syncthreads();  // Vt visible

  // ---- O = P @ V via warp shuffles (P stays in registers) ----
  float acc2[4][4];
  #pragma unroll
  for (int i = 0; i < 4; i++)
    #pragma unroll
    for (int c2 = 0; c2 < 4; c2++) acc2[i][c2] = 0.f;
  {
    const int shb = tid & 16;           // keep shuffle source in same half-warp (same rg)
    const float* vt0 = sm + OFF_A + cg * SV;
    #pragma unroll
    for (int j = 0; j < 16; j++) {
      float a0 = accS[0][j], a1 = accS[1][j], a2 = accS[2][j], a3 = accS[3][j];
      #pragma unroll 1
      for (int m = 0; m < 4; m++) {
        int n = j * 16 + m * 4;
        int s0 = shb + m * 4;
        float p00 = __shfl_sync(0xffffffffu, a0, s0 + 0);
        float p01 = __shfl_sync(0xffffffffu, a0, s0 + 1);
        float p02 = __shfl_sync(0xffffffffu, a0, s0 + 2);
        float p03 = __shfl_sync(0xffffffffu, a0, s0 + 3);
        float p10 = __shfl_sync(0xffffffffu, a1, s0 + 0);
        float p11 = __shfl_sync(0xffffffffu, a1, s0 + 1);
        float p12 = __shfl_sync(0xffffffffu, a1, s0 + 2);
        float p13 = __shfl_sync(0xffffffffu, a1, s0 + 3);
        float p20 = __shfl_sync(0xffffffffu, a2, s0 + 0);
        float p21 = __shfl_sync(0xffffffffu, a2, s0 + 1);
        float p22 = __shfl_sync(0xffffffffu, a2, s0 + 2);
        float p23 = __shfl_sync(0xffffffffu, a2, s0 + 3);
        float p30 = __shfl_sync(0xffffffffu, a3, s0 + 0);
        float p31 = __shfl_sync(0xffffffffu, a3, s0 + 1);
        float p32 = __shfl_sync(0xffffffffu, a3, s0 + 2);
        float p33 = __shfl_sync(0xffffffffu, a3, s0 + 3);
        #pragma unroll
        for (int c2 = 0; c2 < 4; c2++) {
          float4 vv = *(const float4*)(vt0 + c2 * (16 * SV) + n);
          acc2[0][c2] = fmaf(p00, vv.x, fmaf(p01, vv.y, fmaf(p02, vv.z, fmaf(p03, vv.w, acc2[0][c2]))));
          acc2[1][c2] = fmaf(p10, vv.x, fmaf(p11, vv.y, fmaf(p12, vv.z, fmaf(p13, vv.w, acc2[1][c2]))));
          acc2[2][c2] = fmaf(p20, vv.x, fmaf(p21, vv.y, fmaf(p22, vv.z, fmaf(p23, vv.w, acc2[2][c2]))));
          acc2[3][c2] = fmaf(p30, vv.x, fmaf(p31, vv.y, fmaf(p32, vv.z, fmaf(p33, vv.w, acc2[3][c2]))));
        }
      }
    }
  }

  // ---- residual (+v at query row) + LayerNorm 1 ----
  float z[4][4];
  {
    float sum[4], sq[4];
    #pragma unroll
    for (int i = 0; i < 4; i++) { sum[i] = 0.f; sq[i] = 0.f; }
    #pragma unroll
    for (int i = 0; i < 4; i++) {
      int n = rb + rg * 4 + i;
      #pragma unroll
      for (int c2 = 0; c2 < 4; c2++) {
        float o = acc2[i][c2] + sm[OFF_A + (cg + 16 * c2) * SV + n];
        z[i][c2] = o;
        sum[i] += o;
        sq[i]  += o * o;
      }
    }
    #pragma unroll
    for (int i = 0; i < 4; i++) { sum[i] = hsum16(sum[i]); sq[i] = hsum16(sq[i]); }
    #pragma unroll
    for (int i = 0; i < 4; i++) {
      float mean = sum[i] * (1.f / 64.f);
      float var  = sq[i] * (1.f / 64.f) - mean * mean;
      float rs = rsqrtf(var + 1e-5f);
      #pragma unroll
      for (int c2 = 0; c2 < 4; c2++) {
        int c = cg + 16 * c2;
        z[i][c2] = (z[i][c2] - mean) * rs * sm[C_G0 + c] + sm[C_B0 + c];
      }
    }
  }
  __syncthreads();  // Vt dead; A region free

  // ---- stage z; load W1,W2 transposed: Wt[c][d] ----
  #pragma unroll
  for (int i = 0; i < 4; i++)
    #pragma unroll
    for (int c2 = 0; c2 < 4; c2++)
      sm[OFF_Z + (rg * 4 + i) * SA + cg + 16 * c2] = z[i][c2];
  {
    const float4* w1s = (const float4*)w1;
    const float4* w2s = (const float4*)w2;
    #pragma unroll
    for (int it = 0; it < 4; it++) {
      int i = tid + it * NT;
      int d = i >> 4, c4 = (i & 15) << 2;
      float4 v = __ldg(w1s + i);
      float* bp = sm + OFF_W1 + c4 * SA + d;
      bp[0 * SA] = v.x; bp[1 * SA] = v.y; bp[2 * SA] = v.z; bp[3 * SA] = v.w;
      v = __ldg(w2s + i);
      bp = sm + OFF_W2 + c4 * SA + d;
      bp[0 * SA] = v.x; bp[1 * SA] = v.y; bp[2 * SA] = v.z; bp[3 * SA] = v.w;
    }
  }
  __syncthreads();

  // ---- FFN layer 1: h = relu(z @ W1 + b1) ----
  {
    float hacc[4][4];
    #pragma unroll
    for (int i = 0; i < 4; i++)
      #pragma unroll
      for (int c2 = 0; c2 < 4; c2++) hacc[i][c2] = sm[C_F1B + cg + 16 * c2];
    const float* z0 = sm + OFF_Z + (rg * 4 + 0) * SA;
    const float* z1 = sm + OFF_Z + (rg * 4 + 1) * SA;
    const float* z2 = sm + OFF_Z + (rg * 4 + 2) * SA;
    const float* z3 = sm + OFF_Z + (rg * 4 + 3) * SA;
    const float* wb = sm + OFF_W1 + cg * SA;
    #pragma unroll 2
    for (int d4 = 0; d4 < 64; d4 += 4) {
      float4 a0 = *(const float4*)(z0 + d4);
      float4 a1 = *(const float4*)(z1 + d4);
      float4 a2 = *(const float4*)(z2 + d4);
      float4 a3 = *(const float4*)(z3 + d4);
      #pragma unroll
      for (int c2 = 0; c2 < 4; c2++) {
        float4 w = *(const float4*)(wb + c2 * (16 * SA) + d4);
        hacc[0][c2] = fmaf(a0.x, w.x, fmaf(a0.y, w.y, fmaf(a0.z, w.z, fmaf(a0.w, w.w, hacc[0][c2]))));
        hacc[1][c2] = fmaf(a1.x, w.x, fmaf(a1.y, w.y, fmaf(a1.z, w.z, fmaf(a1.w, w.w, hacc[1][c2]))));
        hacc[2][c2] = fmaf(a2.x, w.x, fmaf(a2.y, w.y, fmaf(a2.z, w.z, fmaf(a2.w, w.w, hacc[2][c2]))));
        hacc[3][c2] = fmaf(a3.x, w.x, fmaf(a3.y, w.y, fmaf(a3.z, w.z, fmaf(a3.w, w.w, hacc[3][c2]))));
      }
    }
    #pragma unroll
    for (int i = 0; i < 4; i++)
      #pragma unroll
      for (int c2 = 0; c2 < 4; c2++)
        sm[OFF_H + (rg * 4 + i) * SA + cg + 16 * c2] = fmaxf(hacc[i][c2], 0.f);
  }
  __syncthreads();

  // ---- FFN layer 2 + residual + LayerNorm 2 + store ----
  {
    float f[4][4];
    #pragma unroll
    for (int i = 0; i < 4; i++)
      #pragma unroll
      for (int c2 = 0; c2 < 4; c2++) f[i][c2] = sm[C_F2B + cg + 16 * c2];
    const float* h0 = sm + OFF_H + (rg * 4 + 0) * SA;
    const float* h1 = sm + OFF_H + (rg * 4 + 1) * SA;
    const float* h2 = sm + OFF_H + (rg * 4 + 2) * SA;
    const float* h3 = sm + OFF_H + (rg * 4 + 3) * SA;
    const float* wb = sm + OFF_W2 + cg * SA;
    #pragma unroll 2
    for (int d4 = 0; d4 < 64; d4 += 4) {
      float4 a0 = *(const float4*)(h0 + d4);
      float4 a1 = *(const float4*)(h1 + d4);
      float4 a2 = *(const float4*)(h2 + d4);
      float4 a3 = *(const float4*)(h3 + d4);
      #pragma unroll
      for (int c2 = 0; c2 < 4; c2++) {
        float4 w = *(const float4*)(wb + c2 * (16 * SA) + d4);
        f[0][c2] = fmaf(a0.x, w.x, fmaf(a0.y, w.y, fmaf(a0.z, w.z, fmaf(a0.w, w.w, f[0][c2]))));
        f[1][c2] = fmaf(a1.x, w.x, fmaf(a1.y, w.y, fmaf(a1.z, w.z, fmaf(a1.w, w.w, f[1][c2]))));
        f[2][c2] = fmaf(a2.x, w.x, fmaf(a2.y, w.y, fmaf(a2.z, w.z, fmaf(a2.w, w.w, f[2][c2]))));
        f[3][c2] = fmaf(a3.x, w.x, fmaf(a3.y, w.y, fmaf(a3.z, w.z, fmaf(a3.w, w.w, f[3][c2]))));
      }
    }
    float sum[4], sq[4];
    #pragma unroll
    for (int i = 0; i < 4; i++) { sum[i] = 0.f; sq[i] = 0.f; }
    #pragma unroll
    for (int i = 0; i < 4; i++)
      #pragma unroll
      for (int c2 = 0; c2 < 4; c2++) {
        float o = f[i][c2] + z[i][c2];
        f[i][c2] = o;
        sum[i] += o;
        sq[i]  += o * o;
      }
    #pragma unroll
    for (int i = 0; i < 4; i++) { sum[i] = hsum16(sum[i]); sq[i] = hsum16(sq[i]); }
    #pragma unroll
    for (int i = 0; i < 4; i++) {
      float mean = sum[i] * (1.f / 64.f);
      float var  = sq[i] * (1.f / 64.f) - mean * mean;
      float rs = rsqrtf(var + 1e-5f);
      float* orow = outG + (size_t)(rb + rg * 4 + i) * Cn;
      #pragma unroll
      for (int c2 = 0; c2 < 4; c2++) {
        int c = cg + 16 * c2;
        orow[c] = (f[i][c2] - mean) * rs * sm[C_G1 + c] + sm[C_B1 + c];
      }
    }
  }
}

extern "C" void kernel_launch(void* const* d_in, const int* in_sizes, int n_in,
                              void* d_out, int out_size) {
  (void)in_sizes; (void)n_in; (void)out_size;
  const float* x   = (const float*)d_in[0];
  const float* emb = (const float*)d_in[1];
  const float* Wk  = (const float*)d_in[2];
  const float* bk  = (const float*)d_in[3];
  const float* Wq  = (const float*)d_in[4];
  const float* bq  = (const float*)d_in[5];
  const float* Wv  = (const float*)d_in[6];
  const float* bv  = (const float*)d_in[7];

  AttnParams p;
  p.g0x  = (const float*)d_in[8];   p.b0x = (const float*)d_in[9];
  p.g1x  = (const float*)d_in[10];  p.b1x = (const float*)d_in[11];
  p.g0k  = (const float*)d_in[12];  p.b0k = (const float*)d_in[13];
  p.g1k  = (const float*)d_in[14];  p.b1k = (const float*)d_in[15];
  p.g0q  = (const float*)d_in[16];  p.b0q = (const float*)d_in[17];
  p.g1q  = (const float*)d_in[18];  p.b1q = (const float*)d_in[19];
  p.fx1w = (const float*)d_in[20];  p.fx1b = (const float*)d_in[21];
  p.fx2w = (const float*)d_in[22];  p.fx2b = (const float*)d_in[23];
  p.fk1w = (const float*)d_in[24];  p.fk1b = (const float*)d_in[25];
  p.fk2w = (const float*)d_in[26];  p.fk2b = (const float*)d_in[27];
  p.fq1w = (const float*)d_in[28];  p.fq1b = (const float*)d_in[29];
  p.fq2w = (const float*)d_in[30];  p.fq2b = (const float*)d_in[31];

  float* out = (float*)d_out;
  p.K = out;
  p.Q = out + SZ;
  p.V = out + 2 * SZ;
  p.t = 0;

  cudaFuncSetAttribute((const void*)attn_step_kernel,
                       cudaFuncAttributeMaxDynamicSharedMemorySize, SMEM_BYTES);

  // all raw projections (and K/Q/V at t=0) in one launch: B*NUM*L*H / NT blocks
  precompute_raw_kernel<<<(Bn * NUMn * Ln * 8) / NT, NT>>>(x, emb, Wk, bk, Wq, bq, Wv, bv,
                                                           p.K, p.Q, p.V);

  for (int t = 1; t < NUMn; t++) {
    p.t = t;
    // phase A: k-attn (mode 0) and q-attn (mode 1) are independent
    attn_step_kernel<<<dim3(Ln / RB, Bn, 2), NT, SMEM_BYTES>>>(p, 0);
    // phase B: v-attn (mode 2) depends on freshly written K[t] and Q[t]
    attn_step_kernel<<<dim3(Ln / RB, Bn, 1), NT, SMEM_BYTES>>>(p, 2);
  }
}

// round 10
// speedup vs baseline: 1.8284x; 1.0718x over previous
#include <cuda_runtime.h>

// ---------------- problem constants ----------------
#define Ln   256
#define Cn   64
#define NUMn 64
#define Bn   32
#define NT   256
#define SA   68    // row stride (floats): 272B % 128 == 16 -> conflict-free LDS.128 phases
#define SV   260   // row stride (floats) for transposed K/V: 1040B % 128 == 16

#define SZ (33554432ULL)  // B*NUM*L*C per tensor

// raw per-head projections of (x + emb) for all (b,t): [k|q|v][b][t][l][c]
__device__ float g_raw[3ULL * SZ];

// ---------------- shared memory layout (floats) ----------------
// OFF_A (17408 fl): Kt[64][SV] -> Vt[64][SV] -> {z,h,W1t,W2t}[64][SA] each
#define OFF_A  0
#define OFF_Z  (OFF_A)
#define OFF_H  (OFF_A + 64*SA)
#define OFF_W1 (OFF_A + 128*SA)
#define OFF_W2 (OFF_A + 192*SA)
#define OFF_P  (OFF_A + 256*SA)   // 4352 fl: Q staging [RB][SA] -> P chunk [RB][SA]
#define OFF_C  (OFF_P + 64*SA)
#define C_G0   (OFF_C + 0)
#define C_B0   (OFF_C + 64)
#define C_G1   (OFF_C + 128)
#define C_B1   (OFF_C + 192)
#define C_F1B  (OFF_C + 256)
#define C_F2B  (OFF_C + 320)
#define SMEM_FLOATS (OFF_C + 384)
#define SMEM_BYTES  (SMEM_FLOATS * 4)   // 88,576 B -> 2 CTAs/SM

typedef unsigned long long u64t;

__device__ __forceinline__ u64t fma2(u64t a, u64t b, u64t c) {
  u64t d; asm("fma.rn.f32x2 %0, %1, %2, %3;" : "=l"(d) : "l"(a), "l"(b), "l"(c)); return d;
}
__device__ __forceinline__ u64t pack2(float x, float y) {
  u64t d; asm("mov.b64 %0, {%1, %2};" : "=l"(d) : "f"(x), "f"(y)); return d;
}
__device__ __forceinline__ float2 unpack2(u64t v) {
  float2 r; asm("mov.b64 {%0, %1}, %2;" : "=f"(r.x), "=f"(r.y) : "l"(v)); return r;
}
__device__ __forceinline__ float f4c(const float4& v, int k) {
  return (k == 0) ? v.x : (k == 1) ? v.y : (k == 2) ? v.z : v.w;
}

struct AttnParams {
  const float *g0x, *b0x, *g1x, *b1x;
  const float *g0k, *b0k, *g1k, *b1k;
  const float *g0q, *b0q, *g1q, *b1q;
  const float *fx1w, *fx1b, *fx2w, *fx2b;
  const float *fk1w, *fk1b, *fk2w, *fk2b;
  const float *fq1w, *fq1b, *fq2w, *fq2b;
  float *K, *Q, *V;
  int t;
};

__device__ __forceinline__ float hmax16(float v) {
  v = fmaxf(v, __shfl_xor_sync(0xffffffffu, v, 1));
  v = fmaxf(v, __shfl_xor_sync(0xffffffffu, v, 2));
  v = fmaxf(v, __shfl_xor_sync(0xffffffffu, v, 4));
  v = fmaxf(v, __shfl_xor_sync(0xffffffffu, v, 8));
  return v;
}
__device__ __forceinline__ float hsum16(float v) {
  v += __shfl_xor_sync(0xffffffffu, v, 1);
  v += __shfl_xor_sync(0xffffffffu, v, 2);
  v += __shfl_xor_sync(0xffffffffu, v, 4);
  v += __shfl_xor_sync(0xffffffffu, v, 8);
  return v;
}

// gather-transpose: src [256][64] row-major gmem -> dst [64][SV] smem (c-major)
// 4096 float4-stores total: i = 0..4095, c = i & 63, n4 = (i>>6)*4 (0..252)
__device__ __forceinline__ void load_transposed_LxC(float* dst, const float* __restrict__ src, int tid) {
  #pragma unroll
  for (int it = 0; it < 16; it++) {
    int i = tid + it * NT;          // 0..4095
    int c  = i & 63;
    int n4 = (i >> 6) << 2;
    float v0 = __ldg(src + (n4 + 0) * 64 + c);
    float v1 = __ldg(src + (n4 + 1) * 64 + c);
    float v2 = __ldg(src + (n4 + 2) * 64 + c);
    float v3 = __ldg(src + (n4 + 3) * 64 + c);
    *(float4*)(dst + c * SV + n4) = make_float4(v0, v1, v2, v3);
  }
}

// gather-transpose: W [64][64] gmem [d][c] -> Wt [64][SA] smem [c][d]
// 1024 float4-stores total: i = 0..1023, c = i & 63, d4 = (i>>6)*4 (0..60)
__device__ __forceinline__ void load_W_transposed(float* dst, const float* __restrict__ src, int tid) {
  #pragma unroll
  for (int it = 0; it < 4; it++) {
    int i = tid + it * NT;          // 0..1023
    int c  = i & 63;
    int d4 = (i >> 6) << 2;
    float v0 = __ldg(src + (d4 + 0) * 64 + c);
    float v1 = __ldg(src + (d4 + 1) * 64 + c);
    float v2 = __ldg(src + (d4 + 2) * 64 + c);
    float v3 = __ldg(src + (d4 + 3) * 64 + c);
    *(float4*)(dst + c * SA + d4) = make_float4(v0, v1, v2, v3);
  }
}

// ============ precompute: raw = proj(x + emb) for every (b,t); also K/Q/V at t=0 ============
__global__ __launch_bounds__(NT)
void precompute_raw_kernel(const float* __restrict__ x, const float* __restrict__ emb,
                           const float* __restrict__ Wk, const float* __restrict__ bk,
                           const float* __restrict__ Wq, const float* __restrict__ bq,
                           const float* __restrict__ Wv, const float* __restrict__ bv,
                           float* __restrict__ K, float* __restrict__ Q, float* __restrict__ V) {
  __shared__ float w[3 * 512 + 3 * 64];
  const int tid = threadIdx.x;
  for (int i = tid; i < 512; i += NT) {
    w[i]        = __ldg(Wk + i);
    w[512 + i]  = __ldg(Wq + i);
    w[1024 + i] = __ldg(Wv + i);
  }
  if (tid < 64) {
    w[1536 + tid] = __ldg(bk + tid);
    w[1600 + tid] = __ldg(bq + tid);
    w[1664 + tid] = __ldg(bv + tid);
  }
  __syncthreads();

  const size_t task = (size_t)blockIdx.x * NT + tid;
  const int h = (int)(task & 7);
  const size_t row = task >> 3;
  const int l = (int)(row & 255);
  const int t = (int)((row >> 8) & 63);

  float xe[8];
  const float* xr = x + row * 64 + h * 8;
  const float* er = emb + l * 64 + h * 8;
  #pragma unroll
  for (int d = 0; d < 8; d++) xe[d] = __ldg(xr + d) + __ldg(er + d);

  float* outs0[3] = {K, Q, V};
  #pragma unroll
  for (int pidx = 0; pidx < 3; pidx++) {
    const float* W  = w + pidx * 512 + h * 64;
    const float* bb = w + 1536 + pidx * 64 + h * 8;
    float acc[8];
    #pragma unroll
    for (int e = 0; e < 8; e++) acc[e] = bb[e];
    #pragma unroll
    for (int d = 0; d < 8; d++) {
      float xv = xe[d];
      #pragma unroll
      for (int e = 0; e < 8; e++) acc[e] = fmaf(xv, W[d * 8 + e], acc[e]);
    }
    float* dst = g_raw + (size_t)pidx * SZ + row * 64 + h * 8;
    #pragma unroll
    for (int e = 0; e < 8; e++) dst[e] = acc[e];
    if (t == 0) {
      float* d2 = outs0[pidx] + row * 64 + h * 8;
      #pragma unroll
      for (int e = 0; e < 8; e++) d2[e] = acc[e];
    }
  }
}

// ============ attention step kernel (RPT rows per thread; RB = 16*RPT rows per CTA) ============
// mode 0: k-attn  keys=raw_k[t], vals=raw_k[t], queries=Q[t-1]   -> K[t]
// mode 1: q-attn  keys=K[t-1],   vals=raw_q[t], queries=raw_q[t] -> Q[t]
// mode 2: v-attn  keys=K[t],     vals=raw_v[t], queries=Q[t]     -> V[t]
template <int RPT>
__global__ __launch_bounds__(NT, 2)
void attn_step_kernel(AttnParams p, int modeBase) {
  extern __shared__ float sm[];
  const int tid = threadIdx.x;
  const int RB  = 16 * RPT;
  const int rb  = blockIdx.x * RB;
  const int b   = blockIdx.y;
  const int mode = modeBase + (int)blockIdx.z;
  const int t = p.t;

  const size_t bOff    = (size_t)b * NUMn * Ln * Cn;
  const size_t curOff  = bOff + (size_t)t * Ln * Cn;
  const size_t prevOff = bOff + (size_t)(t - 1) * Ln * Cn;
  const float* rawK = g_raw;
  const float* rawQ = g_raw + SZ;
  const float* rawV = g_raw + 2 * SZ;

  const float *g0, *b0, *g1, *b1, *w1, *fb1, *w2, *fb2;
  const float *keysG, *qG, *valsG;
  float* outG;
  if (mode == 0) {
    g0 = p.g0k; b0 = p.b0k; g1 = p.g1k; b1 = p.b1k;
    w1 = p.fk1w; fb1 = p.fk1b; w2 = p.fk2w; fb2 = p.fk2b;
    keysG = rawK + curOff; valsG = rawK + curOff;
    qG = p.Q + prevOff + (size_t)rb * Cn;
    outG = p.K + curOff;
  } else if (mode == 1) {
    g0 = p.g0q; b0 = p.b0q; g1 = p.g1q; b1 = p.b1q;
    w1 = p.fq1w; fb1 = p.fq1b; w2 = p.fq2w; fb2 = p.fq2b;
    keysG = p.K + prevOff; valsG = rawQ + curOff;
    qG = rawQ + curOff + (size_t)rb * Cn;
    outG = p.Q + curOff;
  } else {
    g0 = p.g0x; b0 = p.b0x; g1 = p.g1x; b1 = p.b1x;
    w1 = p.fx1w; fb1 = p.fx1b; w2 = p.fx2w; fb2 = p.fx2b;
    keysG = p.K + curOff; valsG = rawV + curOff;
    qG = p.Q + curOff + (size_t)rb * Cn;
    outG = p.V + curOff;
  }

  // ---- load Kt (transposed), Q rows, consts ----
  load_transposed_LxC(sm + OFF_A, keysG, tid);
  {
    const float4* q4 = (const float4*)qG;
    #pragma unroll
    for (int it = 0; it < RPT; it++) {
      int i = tid + it * NT;         // RB*16 float4s
      float4 v = __ldg(q4 + i);
      int l = i >> 4, c = (i & 15) << 2;
      *(float4*)(sm + OFF_P + l * SA + c) = v;
    }
    if (tid < 64) {
      sm[C_G0  + tid] = __ldg(g0 + tid);
      sm[C_B0  + tid] = __ldg(b0 + tid);
      sm[C_G1  + tid] = __ldg(g1 + tid);
      sm[C_B1  + tid] = __ldg(b1 + tid);
      sm[C_F1B + tid] = __ldg(fb1 + tid);
      sm[C_F2B + tid] = __ldg(fb2 + tid);
    }
  }
  __syncthreads();

  const int rg = tid >> 4;   // 16 row-groups, RPT rows each
  const int cg = tid & 15;   // thread owns S cols 4*cg + 64*q + e  (q=0..3, e=0..3)

  // ---- S = Q @ Kt (RB x 256, k=64), packed f32x2 along n ----
  u64t acc[RPT][4][2];
  #pragma unroll
  for (int i = 0; i < RPT; i++)
    #pragma unroll
    for (int q = 0; q < 4; q++) { acc[i][q][0] = 0ull; acc[i][q][1] = 0ull; }
  {
    const float* qb = sm + OFF_P + (rg * RPT) * SA;
    #pragma unroll 4
    for (int d4 = 0; d4 < 64; d4 += 4) {
      float4 qv[RPT];
      #pragma unroll
      for (int i = 0; i < RPT; i++) qv[i] = *(const float4*)(qb + i * SA + d4);
      #pragma unroll
      for (int dd = 0; dd < 4; dd++) {
        u64t qp[RPT];
        #pragma unroll
        for (int i = 0; i < RPT; i++) { float s = f4c(qv[i], dd); qp[i] = pack2(s, s); }
        const float* kt = sm + OFF_A + (d4 + dd) * SV + 4 * cg;
        #pragma unroll
        for (int q = 0; q < 4; q++) {
          ulonglong2 kv = *(const ulonglong2*)(kt + 64 * q);
          #pragma unroll
          for (int i = 0; i < RPT; i++) {
            acc[i][q][0] = fma2(qp[i], kv.x, acc[i][q][0]);
            acc[i][q][1] = fma2(qp[i], kv.y, acc[i][q][1]);
          }
        }
      }
    }
  }
  __syncthreads();  // Kt reads done; A region free

  // ---- load Vt into A (LDG latency overlaps softmax) ----
  load_transposed_LxC(sm + OFF_A, valsG, tid);

  // ---- softmax in registers, fold /sqrt(64) ----
  float pv[RPT][16];
  #pragma unroll
  for (int i = 0; i < RPT; i++) {
    #pragma unroll
    for (int q = 0; q < 4; q++) {
      float2 e0 = unpack2(acc[i][q][0]);
      float2 e1 = unpack2(acc[i][q][1]);
      pv[i][q * 4 + 0] = e0.x; pv[i][q * 4 + 1] = e0.y;
      pv[i][q * 4 + 2] = e1.x; pv[i][q * 4 + 3] = e1.y;
    }
    float m = pv[i][0];
    #pragma unroll
    for (int j = 1; j < 16; j++) m = fmaxf(m, pv[i][j]);
    m = hmax16(m);
    float s = 0.f;
    #pragma unroll
    for (int j = 0; j < 16; j++) {
      float e = __expf(pv[i][j] - m);
      pv[i][j] = e;
      s += e;
    }
    s = hsum16(s);
    float sc = 0.125f / s;
    #pragma unroll
    for (int j = 0; j < 16; j++) pv[i][j] *= sc;
  }

  // ---- O = P @ V, k processed in 4 chunks of 64 via smem P tile (dead Q region) ----
  u64t acc2[RPT][4];
  #pragma unroll
  for (int i = 0; i < RPT; i++)
    #pragma unroll
    for (int c2 = 0; c2 < 4; c2++) acc2[i][c2] = 0ull;
  #pragma unroll
  for (int q = 0; q < 4; q++) {
    __syncthreads();  // (iter 0: Vt visible, Q reads done) / (iter>0: prior chunk reads done)
    #pragma unroll
    for (int i = 0; i < RPT; i++)
      *(float4*)(sm + OFF_P + (rg * RPT + i) * SA + 4 * cg) =
          make_float4(pv[i][q * 4 + 0], pv[i][q * 4 + 1], pv[i][q * 4 + 2], pv[i][q * 4 + 3]);
    __syncthreads();  // chunk visible
    const float* pb = sm + OFF_P + (rg * RPT) * SA;
    const float* vb = sm + OFF_A + cg * SV + q * 64;
    #pragma unroll 4
    for (int m4 = 0; m4 < 64; m4 += 4) {
      ulonglong2 pp[RPT];
      #pragma unroll
      for (int i = 0; i < RPT; i++) pp[i] = *(const ulonglong2*)(pb + i * SA + m4);
      #pragma unroll
      for (int c2 = 0; c2 < 4; c2++) {
        ulonglong2 vv = *(const ulonglong2*)(vb + c2 * (16 * SV) + m4);
        #pragma unroll
        for (int i = 0; i < RPT; i++) {
          acc2[i][c2] = fma2(pp[i].x, vv.x, acc2[i][c2]);
          acc2[i][c2] = fma2(pp[i].y, vv.y, acc2[i][c2]);
        }
      }
    }
  }

  // ---- residual (+v at query row) + LayerNorm 1 ----
  float z[RPT][4];
  {
    float sum[RPT], sq[RPT];
    #pragma unroll
    for (int i = 0; i < RPT; i++) { sum[i] = 0.f; sq[i] = 0.f; }
    #pragma unroll
    for (int i = 0; i < RPT; i++) {
      int n = rb + rg * RPT + i;
      #pragma unroll
      for (int c2 = 0; c2 < 4; c2++) {
        float2 tacc = unpack2(acc2[i][c2]);
        float o = tacc.x + tacc.y + sm[OFF_A + (cg + 16 * c2) * SV + n];
        z[i][c2] = o;
        sum[i] += o;
        sq[i]  += o * o;
      }
    }
    #pragma unroll
    for (int i = 0; i < RPT; i++) { sum[i] = hsum16(sum[i]); sq[i] = hsum16(sq[i]); }
    #pragma unroll
    for (int i = 0; i < RPT; i++) {
      float mean = sum[i] * (1.f / 64.f);
      float var  = sq[i] * (1.f / 64.f) - mean * mean;
      float rs = rsqrtf(var + 1e-5f);
      #pragma unroll
      for (int c2 = 0; c2 < 4; c2++) {
        int c = cg + 16 * c2;
        z[i][c2] = (z[i][c2] - mean) * rs * sm[C_G0 + c] + sm[C_B0 + c];
      }
    }
  }
  __syncthreads();  // Vt + P dead; A region free

  // ---- stage z; load W1,W2 transposed ----
  #pragma unroll
  for (int i = 0; i < RPT; i++)
    #pragma unroll
    for (int c2 = 0; c2 < 4; c2++)
      sm[OFF_Z + (rg * RPT + i) * SA + cg + 16 * c2] = z[i][c2];
  load_W_transposed(sm + OFF_W1, w1, tid);
  load_W_transposed(sm + OFF_W2, w2, tid);
  __syncthreads();

  // ---- FFN layer 1: h = relu(z @ W1 + b1), packed f32x2 along k ----
  {
    u64t hacc[RPT][4];
    #pragma unroll
    for (int i = 0; i < RPT; i++)
      #pragma unroll
      for (int c2 = 0; c2 < 4; c2++) hacc[i][c2] = 0ull;
    const float* zb = sm + OFF_Z + (rg * RPT) * SA;
    const float* wb = sm + OFF_W1 + cg * SA;
    #pragma unroll 4
    for (int d4 = 0; d4 < 64; d4 += 4) {
      ulonglong2 zz[RPT];
      #pragma unroll
      for (int i = 0; i < RPT; i++) zz[i] = *(const ulonglong2*)(zb + i * SA + d4);
      #pragma unroll
      for (int c2 = 0; c2 < 4; c2++) {
        ulonglong2 ww = *(const ulonglong2*)(wb + c2 * (16 * SA) + d4);
        #pragma unroll
        for (int i = 0; i < RPT; i++) {
          hacc[i][c2] = fma2(zz[i].x, ww.x, hacc[i][c2]);
          hacc[i][c2] = fma2(zz[i].y, ww.y, hacc[i][c2]);
        }
      }
    }
    __syncthreads();  // z reads done before h overwrites region? (h separate; ordering for safety of Wt reads)
    #pragma unroll
    for (int i = 0; i < RPT; i++)
      #pragma unroll
      for (int c2 = 0; c2 < 4; c2++) {
        float2 th = unpack2(hacc[i][c2]);
        float hv = th.x + th.y + sm[C_F1B + cg + 16 * c2];
        sm[OFF_H + (rg * RPT + i) * SA + cg + 16 * c2] = fmaxf(hv, 0.f);
      }
  }
  __syncthreads();

  // ---- FFN layer 2 + residual + LayerNorm 2 + store ----
  {
    u64t facc[RPT][4];
    #pragma unroll
    for (int i = 0; i < RPT; i++)
      #pragma unroll
      for (int c2 = 0; c2 < 4; c2++) facc[i][c2] = 0ull;
    const float* hb = sm + OFF_H + (rg * RPT) * SA;
    const float* wb = sm + OFF_W2 + cg * SA;
    #pragma unroll 4
    for (int d4 = 0; d4 < 64; d4 += 4) {
      ulonglong2 hh[RPT];
      #pragma unroll
      for (int i = 0; i < RPT; i++) hh[i] = *(const ulonglong2*)(hb + i * SA + d4);
      #pragma unroll
      for (int c2 = 0; c2 < 4; c2++) {
        ulonglong2 ww = *(const ulonglong2*)(wb + c2 * (16 * SA) + d4);
        #pragma unroll
        for (int i = 0; i < RPT; i++) {
          facc[i][c2] = fma2(hh[i].x, ww.x, facc[i][c2]);
          facc[i][c2] = fma2(hh[i].y, ww.y, facc[i][c2]);
        }
      }
    }
    float f[RPT][4];
    float sum[RPT], sq[RPT];
    #pragma unroll
    for (int i = 0; i < RPT; i++) { sum[i] = 0.f; sq[i] = 0.f; }
    #pragma unroll
    for (int i = 0; i < RPT; i++)
      #pragma unroll
      for (int c2 = 0; c2 < 4; c2++) {
        float2 tf = unpack2(facc[i][c2]);
        float o = tf.x + tf.y + sm[C_F2B + cg + 16 * c2] + z[i][c2];
        f[i][c2] = o;
        sum[i] += o;
        sq[i]  += o * o;
      }
    #pragma unroll
    for (int i = 0; i < RPT; i++) { sum[i] = hsum16(sum[i]); sq[i] = hsum16(sq[i]); }
    #pragma unroll
    for (int i = 0; i < RPT; i++) {
      float mean = sum[i] * (1.f / 64.f);
      float var  = sq[i] * (1.f / 64.f) - mean * mean;
      float rs = rsqrtf(var + 1e-5f);
      float* orow = outG + (size_t)(rb + rg * RPT + i) * Cn;
      #pragma unroll
      for (int c2 = 0; c2 < 4; c2++) {
        int c = cg + 16 * c2;
        orow[c] = (f[i][c2] - mean) * rs * sm[C_G1 + c] + sm[C_B1 + c];
      }
    }
  }
}

extern "C" void kernel_launch(void* const* d_in, const int* in_sizes, int n_in,
                              void* d_out, int out_size) {
  (void)in_sizes; (void)n_in; (void)out_size;
  const float* x   = (const float*)d_in[0];
  const float* emb = (const float*)d_in[1];
  const float* Wk  = (const float*)d_in[2];
  const float* bk  = (const float*)d_in[3];
  const float* Wq  = (const float*)d_in[4];
  const float* bq  = (const float*)d_in[5];
  const float* Wv  = (const float*)d_in[6];
  const float* bv  = (const float*)d_in[7];

  AttnParams p;
  p.g0x  = (const float*)d_in[8];   p.b0x = (const float*)d_in[9];
  p.g1x  = (const float*)d_in[10];  p.b1x = (const float*)d_in[11];
  p.g0k  = (const float*)d_in[12];  p.b0k = (const float*)d_in[13];
  p.g1k  = (const float*)d_in[14];  p.b1k = (const float*)d_in[15];
  p.g0q  = (const float*)d_in[16];  p.b0q = (const float*)d_in[17];
  p.g1q  = (const float*)d_in[18];  p.b1q = (const float*)d_in[19];
  p.fx1w = (const float*)d_in[20];  p.fx1b = (const float*)d_in[21];
  p.fx2w = (const float*)d_in[22];  p.fx2b = (const float*)d_in[23];
  p.fk1w = (const float*)d_in[24];  p.fk1b = (const float*)d_in[25];
  p.fk2w = (const float*)d_in[26];  p.fk2b = (const float*)d_in[27];
  p.fq1w = (const float*)d_in[28];  p.fq1b = (const float*)d_in[29];
  p.fq2w = (const float*)d_in[30];  p.fq2b = (const float*)d_in[31];

  float* out = (float*)d_out;
  p.K = out;
  p.Q = out + SZ;
  p.V = out + 2 * SZ;
  p.t = 0;

  cudaFuncSetAttribute((const void*)attn_step_kernel<4>,
                       cudaFuncAttributeMaxDynamicSharedMemorySize, SMEM_BYTES);
  cudaFuncSetAttribute((const void*)attn_step_kernel<2>,
                       cudaFuncAttributeMaxDynamicSharedMemorySize, SMEM_BYTES);

  // all raw projections (and K/Q/V at t=0) in one launch
  precompute_raw_kernel<<<(Bn * NUMn * Ln * 8) / NT, NT>>>(x, emb, Wk, bk, Wq, bq, Wv, bv,
                                                           p.K, p.Q, p.V);

  for (int t = 1; t < NUMn; t++) {
    p.t = t;
    // phase A: k-attn (mode 0) and q-attn (mode 1) independent; 256 CTAs, one wave
    attn_step_kernel<4><<<dim3(Ln / 64, Bn, 2), NT, SMEM_BYTES>>>(p, 0);
    // phase B: v-attn needs K[t], Q[t]; RB=32 -> 256 CTAs to fill the machine
    attn_step_kernel<2><<<dim3(Ln / 32, Bn, 1), NT, SMEM_BYTES>>>(p, 2);
  }
}

// round 11
// speedup vs baseline: 1.8841x; 1.0304x over previous
#include <cuda_runtime.h>

// ---------------- problem constants ----------------
#define Ln   256
#define Cn   64
#define NUMn 64
#define Bn   32
#define NT   256
#define SA   68    // row stride (floats): 272B % 128 == 16 -> conflict-free LDS.128 phases
#define SV   260   // row stride (floats) for transposed K/V: 1040B % 128 == 16
#define SP   132   // row stride (floats) for P/Q region: 528B % 128 == 16

#define SZ (33554432ULL)  // B*NUM*L*C per tensor

// raw per-head projections of (x + emb) for all (b,t): [k|q|v][b][t][l][c]
__device__ float g_raw[3ULL * SZ];

// ---------------- shared memory layout (floats) ----------------
// OFF_A (17408 fl): Kt[64][SV] -> Vt[64][SV] -> {z,h,W1t,W2t}[64][SA] each
#define OFF_A  0
#define OFF_Z  (OFF_A)
#define OFF_H  (OFF_A + 64*SA)
#define OFF_W1 (OFF_A + 128*SA)
#define OFF_W2 (OFF_A + 192*SA)
#define OFF_P  (OFF_A + 256*SA)   // 64*SP = 8448 fl: Q staging [RB][SP] -> P 128-col chunk [RB][SP]
#define OFF_C  (OFF_P + 64*SP)
#define C_G0   (OFF_C + 0)
#define C_B0   (OFF_C + 64)
#define C_G1   (OFF_C + 128)
#define C_B1   (OFF_C + 192)
#define C_F1B  (OFF_C + 256)
#define C_F2B  (OFF_C + 320)
#define SMEM_FLOATS (OFF_C + 384)
#define SMEM_BYTES  (SMEM_FLOATS * 4)   // 104,960 B -> 2 CTAs/SM

typedef unsigned long long u64t;

__device__ __forceinline__ u64t fma2(u64t a, u64t b, u64t c) {
  u64t d; asm("fma.rn.f32x2 %0, %1, %2, %3;" : "=l"(d) : "l"(a), "l"(b), "l"(c)); return d;
}
__device__ __forceinline__ u64t pack2(float x, float y) {
  u64t d; asm("mov.b64 %0, {%1, %2};" : "=l"(d) : "f"(x), "f"(y)); return d;
}
__device__ __forceinline__ float2 unpack2(u64t v) {
  float2 r; asm("mov.b64 {%0, %1}, %2;" : "=f"(r.x), "=f"(r.y) : "l"(v)); return r;
}
__device__ __forceinline__ float f4c(const float4& v, int k) {
  return (k == 0) ? v.x : (k == 1) ? v.y : (k == 2) ? v.z : v.w;
}

struct AttnParams {
  const float *g0x, *b0x, *g1x, *b1x;
  const float *g0k, *b0k, *g1k, *b1k;
  const float *g0q, *b0q, *g1q, *b1q;
  const float *fx1w, *fx1b, *fx2w, *fx2b;
  const float *fk1w, *fk1b, *fk2w, *fk2b;
  const float *fq1w, *fq1b, *fq2w, *fq2b;
  float *K, *Q, *V;
  int t;
};

__device__ __forceinline__ float hmax16(float v) {
  v = fmaxf(v, __shfl_xor_sync(0xffffffffu, v, 1));
  v = fmaxf(v, __shfl_xor_sync(0xffffffffu, v, 2));
  v = fmaxf(v, __shfl_xor_sync(0xffffffffu, v, 4));
  v = fmaxf(v, __shfl_xor_sync(0xffffffffu, v, 8));
  return v;
}
__device__ __forceinline__ float hsum16(float v) {
  v += __shfl_xor_sync(0xffffffffu, v, 1);
  v += __shfl_xor_sync(0xffffffffu, v, 2);
  v += __shfl_xor_sync(0xffffffffu, v, 4);
  v += __shfl_xor_sync(0xffffffffu, v, 8);
  return v;
}

// gather-transpose: src [256][64] row-major gmem -> dst [64][SV] smem (c-major)
__device__ __forceinline__ void load_transposed_LxC(float* dst, const float* __restrict__ src, int tid) {
  #pragma unroll
  for (int it = 0; it < 16; it++) {
    int i = tid + it * NT;          // 0..4095
    int c  = i & 63;
    int n4 = (i >> 6) << 2;
    float v0 = __ldg(src + (n4 + 0) * 64 + c);
    float v1 = __ldg(src + (n4 + 1) * 64 + c);
    float v2 = __ldg(src + (n4 + 2) * 64 + c);
    float v3 = __ldg(src + (n4 + 3) * 64 + c);
    *(float4*)(dst + c * SV + n4) = make_float4(v0, v1, v2, v3);
  }
}

// gather-transpose: W [64][64] gmem [d][c] -> Wt [64][SA] smem [c][d]
__device__ __forceinline__ void load_W_transposed(float* dst, const float* __restrict__ src, int tid) {
  #pragma unroll
  for (int it = 0; it < 4; it++) {
    int i = tid + it * NT;          // 0..1023
    int c  = i & 63;
    int d4 = (i >> 6) << 2;
    float v0 = __ldg(src + (d4 + 0) * 64 + c);
    float v1 = __ldg(src + (d4 + 1) * 64 + c);
    float v2 = __ldg(src + (d4 + 2) * 64 + c);
    float v3 = __ldg(src + (d4 + 3) * 64 + c);
    *(float4*)(dst + c * SA + d4) = make_float4(v0, v1, v2, v3);
  }
}

// ============ precompute: raw = proj(x + emb) for every (b,t); also K/Q/V at t=0 ============
__global__ __launch_bounds__(NT)
void precompute_raw_kernel(const float* __restrict__ x, const float* __restrict__ emb,
                           const float* __restrict__ Wk, const float* __restrict__ bk,
                           const float* __restrict__ Wq, const float* __restrict__ bq,
                           const float* __restrict__ Wv, const float* __restrict__ bv,
                           float* __restrict__ K, float* __restrict__ Q, float* __restrict__ V) {
  __shared__ float w[3 * 512 + 3 * 64];
  const int tid = threadIdx.x;
  for (int i = tid; i < 512; i += NT) {
    w[i]        = __ldg(Wk + i);
    w[512 + i]  = __ldg(Wq + i);
    w[1024 + i] = __ldg(Wv + i);
  }
  if (tid < 64) {
    w[1536 + tid] = __ldg(bk + tid);
    w[1600 + tid] = __ldg(bq + tid);
    w[1664 + tid] = __ldg(bv + tid);
  }
  __syncthreads();

  const size_t task = (size_t)blockIdx.x * NT + tid;
  const int h = (int)(task & 7);
  const size_t row = task >> 3;
  const int l = (int)(row & 255);
  const int t = (int)((row >> 8) & 63);

  float xe[8];
  const float* xr = x + row * 64 + h * 8;
  const float* er = emb + l * 64 + h * 8;
  #pragma unroll
  for (int d = 0; d < 8; d++) xe[d] = __ldg(xr + d) + __ldg(er + d);

  float* outs0[3] = {K, Q, V};
  #pragma unroll
  for (int pidx = 0; pidx < 3; pidx++) {
    const float* W  = w + pidx * 512 + h * 64;
    const float* bb = w + 1536 + pidx * 64 + h * 8;
    float acc[8];
    #pragma unroll
    for (int e = 0; e < 8; e++) acc[e] = bb[e];
    #pragma unroll
    for (int d = 0; d < 8; d++) {
      float xv = xe[d];
      #pragma unroll
      for (int e = 0; e < 8; e++) acc[e] = fmaf(xv, W[d * 8 + e], acc[e]);
    }
    float* dst = g_raw + (size_t)pidx * SZ + row * 64 + h * 8;
    #pragma unroll
    for (int e = 0; e < 8; e++) dst[e] = acc[e];
    if (t == 0) {
      float* d2 = outs0[pidx] + row * 64 + h * 8;
      #pragma unroll
      for (int e = 0; e < 8; e++) d2[e] = acc[e];
    }
  }
}

// ============ attention body (RPT rows per thread; RB = 16*RPT rows per CTA) ============
// mode 0: k-attn  keys=raw_k[t], vals=raw_k[t], queries=Q[t-1]   -> K[t]
// mode 1: q-attn  keys=K[t-1],   vals=raw_q[t], queries=raw_q[t] -> Q[t]
// mode 2: v-attn  keys=K[t],     vals=raw_v[t], queries=Q[t]     -> V[t]
template <int RPT>
__device__ __forceinline__ void attn_body(const AttnParams& p, int mode, int t, int rb, float* sm) {
  const int tid = threadIdx.x;
  const int b   = blockIdx.y;

  const size_t bOff    = (size_t)b * NUMn * Ln * Cn;
  const size_t curOff  = bOff + (size_t)t * Ln * Cn;
  const size_t prevOff = bOff + (size_t)(t - 1) * Ln * Cn;
  const float* rawK = g_raw;
  const float* rawQ = g_raw + SZ;
  const float* rawV = g_raw + 2 * SZ;

  const float *g0, *b0, *g1, *b1, *w1, *fb1, *w2, *fb2;
  const float *keysG, *qG, *valsG;
  float* outG;
  if (mode == 0) {
    g0 = p.g0k; b0 = p.b0k; g1 = p.g1k; b1 = p.b1k;
    w1 = p.fk1w; fb1 = p.fk1b; w2 = p.fk2w; fb2 = p.fk2b;
    keysG = rawK + curOff; valsG = rawK + curOff;
    qG = p.Q + prevOff + (size_t)rb * Cn;
    outG = p.K + curOff;
  } else if (mode == 1) {
    g0 = p.g0q; b0 = p.b0q; g1 = p.g1q; b1 = p.b1q;
    w1 = p.fq1w; fb1 = p.fq1b; w2 = p.fq2w; fb2 = p.fq2b;
    keysG = p.K + prevOff; valsG = rawQ + curOff;
    qG = rawQ + curOff + (size_t)rb * Cn;
    outG = p.Q + curOff;
  } else {
    g0 = p.g0x; b0 = p.b0x; g1 = p.g1x; b1 = p.b1x;
    w1 = p.fx1w; fb1 = p.fx1b; w2 = p.fx2w; fb2 = p.fx2b;
    keysG = p.K + curOff; valsG = rawV + curOff;
    qG = p.Q + curOff + (size_t)rb * Cn;
    outG = p.V + curOff;
  }

  // ---- load Kt (transposed), Q rows (stride SP), consts ----
  load_transposed_LxC(sm + OFF_A, keysG, tid);
  {
    const float4* q4 = (const float4*)qG;
    #pragma unroll
    for (int it = 0; it < RPT; it++) {
      int i = tid + it * NT;         // RB*16 float4s
      float4 v = __ldg(q4 + i);
      int l = i >> 4, c = (i & 15) << 2;
      *(float4*)(sm + OFF_P + l * SP + c) = v;
    }
    if (tid < 64) {
      sm[C_G0  + tid] = __ldg(g0 + tid);
      sm[C_B0  + tid] = __ldg(b0 + tid);
      sm[C_G1  + tid] = __ldg(g1 + tid);
      sm[C_B1  + tid] = __ldg(b1 + tid);
      sm[C_F1B + tid] = __ldg(fb1 + tid);
      sm[C_F2B + tid] = __ldg(fb2 + tid);
    }
  }
  __syncthreads();

  const int rg = tid >> 4;   // 16 row-groups, RPT rows each
  const int cg = tid & 15;   // thread owns S cols 4*cg + 64*q + e  (q=0..3, e=0..3)

  // ---- S = Q @ Kt (RB x 256, k=64), packed f32x2 along n ----
  u64t acc[RPT][4][2];
  #pragma unroll
  for (int i = 0; i < RPT; i++)
    #pragma unroll
    for (int q = 0; q < 4; q++) { acc[i][q][0] = 0ull; acc[i][q][1] = 0ull; }
  {
    const float* qb = sm + OFF_P + (rg * RPT) * SP;
    #pragma unroll 4
    for (int d4 = 0; d4 < 64; d4 += 4) {
      float4 qv[RPT];
      #pragma unroll
      for (int i = 0; i < RPT; i++) qv[i] = *(const float4*)(qb + i * SP + d4);
      #pragma unroll
      for (int dd = 0; dd < 4; dd++) {
        u64t qp[RPT];
        #pragma unroll
        for (int i = 0; i < RPT; i++) { float s = f4c(qv[i], dd); qp[i] = pack2(s, s); }
        const float* kt = sm + OFF_A + (d4 + dd) * SV + 4 * cg;
        #pragma unroll
        for (int q = 0; q < 4; q++) {
          ulonglong2 kv = *(const ulonglong2*)(kt + 64 * q);
          #pragma unroll
          for (int i = 0; i < RPT; i++) {
            acc[i][q][0] = fma2(qp[i], kv.x, acc[i][q][0]);
            acc[i][q][1] = fma2(qp[i], kv.y, acc[i][q][1]);
          }
        }
      }
    }
  }
  __syncthreads();  // Kt + Q reads done; A region free

  // ---- load Vt into A (LDG latency overlaps softmax) ----
  load_transposed_LxC(sm + OFF_A, valsG, tid);

  // ---- softmax in registers, fold /sqrt(64) ----
  float pv[RPT][16];
  #pragma unroll
  for (int i = 0; i < RPT; i++) {
    #pragma unroll
    for (int q = 0; q < 4; q++) {
      float2 e0 = unpack2(acc[i][q][0]);
      float2 e1 = unpack2(acc[i][q][1]);
      pv[i][q * 4 + 0] = e0.x; pv[i][q * 4 + 1] = e0.y;
      pv[i][q * 4 + 2] = e1.x; pv[i][q * 4 + 3] = e1.y;
    }
    float m = pv[i][0];
    #pragma unroll
    for (int j = 1; j < 16; j++) m = fmaxf(m, pv[i][j]);
    m = hmax16(m);
    float s = 0.f;
    #pragma unroll
    for (int j = 0; j < 16; j++) {
      float e = __expf(pv[i][j] - m);
      pv[i][j] = e;
      s += e;
    }
    s = hsum16(s);
    float sc = 0.125f / s;
    #pragma unroll
    for (int j = 0; j < 16; j++) pv[i][j] *= sc;
  }

  // ---- O = P @ V, k in 2 chunks of 128 via smem P tile (dead Q region) ----
  u64t acc2[RPT][4];
  #pragma unroll
  for (int i = 0; i < RPT; i++)
    #pragma unroll
    for (int c2 = 0; c2 < 4; c2++) acc2[i][c2] = 0ull;
  #pragma unroll
  for (int ch = 0; ch < 2; ch++) {
    __syncthreads();  // ch0: Vt stores + Q reads complete; ch1: chunk-0 reads complete
    #pragma unroll
    for (int i = 0; i < RPT; i++) {
      float* pr = sm + OFF_P + (rg * RPT + i) * SP;
      *(float4*)(pr + 4 * cg) =
          make_float4(pv[i][(2*ch)*4 + 0], pv[i][(2*ch)*4 + 1], pv[i][(2*ch)*4 + 2], pv[i][(2*ch)*4 + 3]);
      *(float4*)(pr + 64 + 4 * cg) =
          make_float4(pv[i][(2*ch+1)*4 + 0], pv[i][(2*ch+1)*4 + 1], pv[i][(2*ch+1)*4 + 2], pv[i][(2*ch+1)*4 + 3]);
    }
    __syncthreads();  // chunk visible
    const float* pb = sm + OFF_P + (rg * RPT) * SP;
    const float* vb = sm + OFF_A + cg * SV + ch * 128;
    #pragma unroll 4
    for (int m4 = 0; m4 < 128; m4 += 4) {
      ulonglong2 pp[RPT];
      #pragma unroll
      for (int i = 0; i < RPT; i++) pp[i] = *(const ulonglong2*)(pb + i * SP + m4);
      #pragma unroll
      for (int c2 = 0; c2 < 4; c2++) {
        ulonglong2 vv = *(const ulonglong2*)(vb + c2 * (16 * SV) + m4);
        #pragma unroll
        for (int i = 0; i < RPT; i++) {
          acc2[i][c2] = fma2(pp[i].x, vv.x, acc2[i][c2]);
          acc2[i][c2] = fma2(pp[i].y, vv.y, acc2[i][c2]);
        }
      }
    }
  }

  // ---- residual (+v at query row) + LayerNorm 1 ----
  float z[RPT][4];
  {
    float sum[RPT], sq[RPT];
    #pragma unroll
    for (int i = 0; i < RPT; i++) { sum[i] = 0.f; sq[i] = 0.f; }
    #pragma unroll
    for (int i = 0; i < RPT; i++) {
      int n = rb + rg * RPT + i;
      #pragma unroll
      for (int c2 = 0; c2 < 4; c2++) {
        float2 tacc = unpack2(acc2[i][c2]);
        float o = tacc.x + tacc.y + sm[OFF_A + (cg + 16 * c2) * SV + n];
        z[i][c2] = o;
        sum[i] += o;
        sq[i]  += o * o;
      }
    }
    #pragma unroll
    for (int i = 0; i < RPT; i++) { sum[i] = hsum16(sum[i]); sq[i] = hsum16(sq[i]); }
    #pragma unroll
    for (int i = 0; i < RPT; i++) {
      float mean = sum[i] * (1.f / 64.f);
      float var  = sq[i] * (1.f / 64.f) - mean * mean;
      float rs = rsqrtf(var + 1e-5f);
      #pragma unroll
      for (int c2 = 0; c2 < 4; c2++) {
        int c = cg + 16 * c2;
        z[i][c2] = (z[i][c2] - mean) * rs * sm[C_G0 + c] + sm[C_B0 + c];
      }
    }
  }
  __syncthreads();  // Vt + P dead; A region free

  // ---- stage z; load W1,W2 transposed ----
  #pragma unroll
  for (int i = 0; i < RPT; i++)
    #pragma unroll
    for (int c2 = 0; c2 < 4; c2++)
      sm[OFF_Z + (rg * RPT + i) * SA + cg + 16 * c2] = z[i][c2];
  load_W_transposed(sm + OFF_W1, w1, tid);
  load_W_transposed(sm + OFF_W2, w2, tid);
  __syncthreads();

  // ---- FFN layer 1: h = relu(z @ W1 + b1), packed f32x2 along k ----
  {
    u64t hacc[RPT][4];
    #pragma unroll
    for (int i = 0; i < RPT; i++)
      #pragma unroll
      for (int c2 = 0; c2 < 4; c2++) hacc[i][c2] = 0ull;
    const float* zb = sm + OFF_Z + (rg * RPT) * SA;
    const float* wb = sm + OFF_W1 + cg * SA;
    #pragma unroll 4
    for (int d4 = 0; d4 < 64; d4 += 4) {
      ulonglong2 zz[RPT];
      #pragma unroll
      for (int i = 0; i < RPT; i++) zz[i] = *(const ulonglong2*)(zb + i * SA + d4);
      #pragma unroll
      for (int c2 = 0; c2 < 4; c2++) {
        ulonglong2 ww = *(const ulonglong2*)(wb + c2 * (16 * SA) + d4);
        #pragma unroll
        for (int i = 0; i < RPT; i++) {
          hacc[i][c2] = fma2(zz[i].x, ww.x, hacc[i][c2]);
          hacc[i][c2] = fma2(zz[i].y, ww.y, hacc[i][c2]);
        }
      }
    }
    #pragma unroll
    for (int i = 0; i < RPT; i++)
      #pragma unroll
      for (int c2 = 0; c2 < 4; c2++) {
        float2 th = unpack2(hacc[i][c2]);
        float hv = th.x + th.y + sm[C_F1B + cg + 16 * c2];
        sm[OFF_H + (rg * RPT + i) * SA + cg + 16 * c2] = fmaxf(hv, 0.f);
      }
  }
  __syncthreads();

  // ---- FFN layer 2 + residual + LayerNorm 2 + store ----
  {
    u64t facc[RPT][4];
    #pragma unroll
    for (int i = 0; i < RPT; i++)
      #pragma unroll
      for (int c2 = 0; c2 < 4; c2++) facc[i][c2] = 0ull;
    const float* hb = sm + OFF_H + (rg * RPT) * SA;
    const float* wb = sm + OFF_W2 + cg * SA;
    #pragma unroll 4
    for (int d4 = 0; d4 < 64; d4 += 4) {
      ulonglong2 hh[RPT];
      #pragma unroll
      for (int i = 0; i < RPT; i++) hh[i] = *(const ulonglong2*)(hb + i * SA + d4);
      #pragma unroll
      for (int c2 = 0; c2 < 4; c2++) {
        ulonglong2 ww = *(const ulonglong2*)(wb + c2 * (16 * SA) + d4);
        #pragma unroll
        for (int i = 0; i < RPT; i++) {
          facc[i][c2] = fma2(hh[i].x, ww.x, facc[i][c2]);
          facc[i][c2] = fma2(hh[i].y, ww.y, facc[i][c2]);
        }
      }
    }
    float f[RPT][4];
    float sum[RPT], sq[RPT];
    #pragma unroll
    for (int i = 0; i < RPT; i++) { sum[i] = 0.f; sq[i] = 0.f; }
    #pragma unroll
    for (int i = 0; i < RPT; i++)
      #pragma unroll
      for (int c2 = 0; c2 < 4; c2++) {
        float2 tf = unpack2(facc[i][c2]);
        float o = tf.x + tf.y + sm[C_F2B + cg + 16 * c2] + z[i][c2];
        f[i][c2] = o;
        sum[i] += o;
        sq[i]  += o * o;
      }
    #pragma unroll
    for (int i = 0; i < RPT; i++) { sum[i] = hsum16(sum[i]); sq[i] = hsum16(sq[i]); }
    #pragma unroll
    for (int i = 0; i < RPT; i++) {
      float mean = sum[i] * (1.f / 64.f);
      float var  = sq[i] * (1.f / 64.f) - mean * mean;
      float rs = rsqrtf(var + 1e-5f);
      float* orow = outG + (size_t)(rb + rg * RPT + i) * Cn;
      #pragma unroll
      for (int c2 = 0; c2 < 4; c2++) {
        int c = cg + 16 * c2;
        orow[c] = (f[i][c2] - mean) * rs * sm[C_G1 + c] + sm[C_B1 + c];
      }
    }
  }
}

// job 0: A(t)            grid (4,32,2): z -> mode 0/1 at t, RPT=4
// job 1: B(t) + A(t+1)   grid (8,32,3): z=0/1 -> mode 0/1 at t+1 (RPT=4, x<4); z=2 -> mode 2 at t (RPT=2, x<8)
// job 2: B(t)            grid (8,32,1): mode 2 at t, RPT=2
__global__ __launch_bounds__(NT, 2)
void attn_step_kernel(AttnParams p, int job) {
  extern __shared__ float sm[];
  const int z  = (int)blockIdx.z;
  const int bx = (int)blockIdx.x;
  if (job == 1) {
    if (z < 2) {
      if (bx >= 4) return;
      attn_body<4>(p, z, p.t + 1, bx * 64, sm);
    } else {
      attn_body<2>(p, 2, p.t, bx * 32, sm);
    }
  } else if (job == 0) {
    attn_body<4>(p, z, p.t, bx * 64, sm);
  } else {
    attn_body<2>(p, 2, p.t, bx * 32, sm);
  }
}

extern "C" void kernel_launch(void* const* d_in, const int* in_sizes, int n_in,
                              void* d_out, int out_size) {
  (void)in_sizes; (void)n_in; (void)out_size;
  const float* x   = (const float*)d_in[0];
  const float* emb = (const float*)d_in[1];
  const float* Wk  = (const float*)d_in[2];
  const float* bk  = (const float*)d_in[3];
  const float* Wq  = (const float*)d_in[4];
  const float* bq  = (const float*)d_in[5];
  const float* Wv  = (const float*)d_in[6];
  const float* bv  = (const float*)d_in[7];

  AttnParams p;
  p.g0x  = (const float*)d_in[8];   p.b0x = (const float*)d_in[9];
  p.g1x  = (const float*)d_in[10];  p.b1x = (const float*)d_in[11];
  p.g0k  = (const float*)d_in[12];  p.b0k = (const float*)d_in[13];
  p.g1k  = (const float*)d_in[14];  p.b1k = (const float*)d_in[15];
  p.g0q  = (const float*)d_in[16];  p.b0q = (const float*)d_in[17];
  p.g1q  = (const float*)d_in[18];  p.b1q = (const float*)d_in[19];
  p.fx1w = (const float*)d_in[20];  p.fx1b = (const float*)d_in[21];
  p.fx2w = (const float*)d_in[22];  p.fx2b = (const float*)d_in[23];
  p.fk1w = (const float*)d_in[24];  p.fk1b = (const float*)d_in[25];
  p.fk2w = (const float*)d_in[26];  p.fk2b = (const float*)d_in[27];
  p.fq1w = (const float*)d_in[28];  p.fq1b = (const float*)d_in[29];
  p.fq2w = (const float*)d_in[30];  p.fq2b = (const float*)d_in[31];

  float* out = (float*)d_out;
  p.K = out;
  p.Q = out + SZ;
  p.V = out + 2 * SZ;

  cudaFuncSetAttribute((const void*)attn_step_kernel,
                       cudaFuncAttributeMaxDynamicSharedMemorySize, SMEM_BYTES);

  // all raw projections (and K/Q/V at t=0) in one launch
  precompute_raw_kernel<<<(Bn * NUMn * Ln * 8) / NT, NT>>>(x, emb, Wk, bk, Wq, bq, Wv, bv,
                                                           p.K, p.Q, p.V);

  // A(1)
  p.t = 1;
  attn_step_kernel<<<dim3(4, Bn, 2), NT, SMEM_BYTES>>>(p, 0);
  // merged B(t) + A(t+1), t = 1..62
  for (int t = 1; t <= 62; t++) {
    p.t = t;
    attn_step_kernel<<<dim3(8, Bn, 3), NT, SMEM_BYTES>>>(p, 1);
  }
  // B(63)
  p.t = 63;
  attn_step_kernel<<<dim3(8, Bn, 1), NT, SMEM_BYTES>>>(p, 2);
}